// round 5
// baseline (speedup 1.0000x reference)
#include <cuda_runtime.h>
#include <cuda_bf16.h>
#include <math.h>

#define NN 50000
#define NE 800000
#define D1 128
#define D2 32

// ---------------- scratch (device globals; no allocations) ----------------
__device__ __align__(16) float g_Wh1[(size_t)NN * D1];
__device__ __align__(16) float g_out1[(size_t)NN * D1];
__device__ __align__(16) float g_Wh2[(size_t)NN * D2];
__device__ __align__(16) float g_out2[(size_t)NN * D2];
__device__ float g_es1[NN], g_ed1[NN];
__device__ float g_es2[NN], g_ed2[NN];
__device__ float g_edgebuf[NE];   // logits, then exp(logit - max) in place
__device__ float g_asum[NN];
__device__ unsigned g_maxkey;

// order-preserving float->uint key (monotone under unsigned compare)
__device__ __forceinline__ unsigned f2key(float f) {
    unsigned b = __float_as_uint(f);
    return (b & 0x80000000u) ? ~b : (b | 0x80000000u);
}
__device__ __forceinline__ float key2f(unsigned k) {
    unsigned b = (k & 0x80000000u) ? (k ^ 0x80000000u) : ~k;
    return __uint_as_float(b);
}

// ---------------- layer 1: Wh1 = x @ W1, e_src/e_dst, zero accumulators ----
__global__ void k_node1(const float* __restrict__ x,
                        const float* __restrict__ W1,
                        const float* __restrict__ a1) {
    __shared__ float sW[8 * D1];
    __shared__ float sa[2 * D1];
    int tid = threadIdx.x;
    for (int i = tid; i < 8 * D1; i += blockDim.x) sW[i] = W1[i];
    for (int i = tid; i < 2 * D1; i += blockDim.x) sa[i] = a1[i];
    __syncthreads();

    if (blockIdx.x == 0 && tid == 0) g_maxkey = 0u;  // reset global max

    int warp = tid >> 5, lane = tid & 31;
    int node = blockIdx.x * (blockDim.x >> 5) + warp;
    if (node >= NN) return;

    float xr[8];
#pragma unroll
    for (int k = 0; k < 8; k++) xr[k] = x[node * 8 + k];

    float es = 0.f, ed = 0.f;
#pragma unroll
    for (int i = 0; i < 4; i++) {
        int j = i * 32 + lane;
        float acc = 0.f;
#pragma unroll
        for (int k = 0; k < 8; k++) acc += xr[k] * sW[k * D1 + j];
        g_Wh1[(size_t)node * D1 + j] = acc;
        g_out1[(size_t)node * D1 + j] = 0.f;
        es += acc * sa[j];
        ed += acc * sa[D1 + j];
    }
#pragma unroll
    for (int o = 16; o; o >>= 1) {
        es += __shfl_down_sync(0xffffffffu, es, o);
        ed += __shfl_down_sync(0xffffffffu, ed, o);
    }
    if (lane == 0) {
        g_es1[node] = es;
        g_ed1[node] = ed;
        g_asum[node] = 0.f;
    }
}

// ---------------- edge logits + global max -------------------------------
// layer flag selects which es/ed tables (device globals referenced in
// device code only).
__global__ void k_logit_max(const int* __restrict__ src,
                            const int* __restrict__ dst,
                            int layer) {
    const float* es = (layer == 1) ? g_es1 : g_es2;
    const float* ed = (layer == 1) ? g_ed1 : g_ed2;
    int e = blockIdx.x * blockDim.x + threadIdx.x;
    float v = -3.0e38f;
    if (e < NE) {
        int s = src[e], d = dst[e];
        float t = es[s] + ed[d];
        v = (t > 0.f) ? t : 0.2f * t;  // leaky_relu, slope 0.2
        g_edgebuf[e] = v;
    }
    unsigned key = f2key(v);
#pragma unroll
    for (int o = 16; o; o >>= 1)
        key = max(key, __shfl_down_sync(0xffffffffu, key, o));
    if ((threadIdx.x & 31) == 0) atomicMax(&g_maxkey, key);
}

// ---------------- exp(logit - max) + segment sum over dst -----------------
__global__ void k_exp_sum(const int* __restrict__ dst) {
    int e = blockIdx.x * blockDim.x + threadIdx.x;
    if (e >= NE) return;
    float m = key2f(g_maxkey);
    float v = expf(g_edgebuf[e] - m);
    g_edgebuf[e] = v;
    atomicAdd(&g_asum[dst[e]], v);
}

// ---------------- aggregation D=128: warp per edge ------------------------
__global__ void k_agg1(const int* __restrict__ src,
                       const int* __restrict__ dst) {
    int t = blockIdx.x * blockDim.x + threadIdx.x;
    int e = t >> 5;
    int lane = t & 31;
    if (e >= NE) return;
    int s = src[e], d = dst[e];
    float coef = g_edgebuf[e] / (g_asum[d] + 1e-9f);
    float4 v = reinterpret_cast<const float4*>(g_Wh1 + (size_t)s * D1)[lane];
    float* o = g_out1 + (size_t)d * D1 + lane * 4;
    atomicAdd(o + 0, coef * v.x);
    atomicAdd(o + 1, coef * v.y);
    atomicAdd(o + 2, coef * v.z);
    atomicAdd(o + 3, coef * v.w);
}

// ---------------- layer 2 node kernel: elu(out1) @ W2, e2, zero accum -----
__global__ void k_node2(const float* __restrict__ W2,
                        const float* __restrict__ a2) {
    __shared__ float sW[D1 * D2];       // 16 KB
    __shared__ float sa[2 * D2];
    __shared__ float sh[8][D1];         // per-warp h row
    int tid = threadIdx.x;
    for (int i = tid; i < D1 * D2; i += blockDim.x) sW[i] = W2[i];
    for (int i = tid; i < 2 * D2; i += blockDim.x) sa[i] = a2[i];
    __syncthreads();

    if (blockIdx.x == 0 && tid == 0) g_maxkey = 0u;  // reset for layer 2

    int warp = tid >> 5, lane = tid & 31;
    int node = blockIdx.x * (blockDim.x >> 5) + warp;
    if (node >= NN) return;

#pragma unroll
    for (int i = 0; i < 4; i++) {
        float v = g_out1[(size_t)node * D1 + i * 32 + lane];
        v = (v > 0.f) ? v : expm1f(v);  // elu
        sh[warp][i * 32 + lane] = v;
    }
    __syncwarp();

    int j = lane;
    float acc = 0.f;
#pragma unroll 8
    for (int k = 0; k < D1; k++) acc += sh[warp][k] * sW[k * D2 + j];

    g_Wh2[(size_t)node * D2 + j] = acc;
    g_out2[(size_t)node * D2 + j] = 0.f;

    float es = acc * sa[j];
    float ed = acc * sa[D2 + j];
#pragma unroll
    for (int o = 16; o; o >>= 1) {
        es += __shfl_down_sync(0xffffffffu, es, o);
        ed += __shfl_down_sync(0xffffffffu, ed, o);
    }
    if (lane == 0) {
        g_es2[node] = es;
        g_ed2[node] = ed;
        g_asum[node] = 0.f;
    }
}

// ---------------- aggregation D=32: 8 lanes per edge ----------------------
__global__ void k_agg2(const int* __restrict__ src,
                       const int* __restrict__ dst) {
    int t = blockIdx.x * blockDim.x + threadIdx.x;
    int e = t >> 3;
    int sub = t & 7;
    if (e >= NE) return;
    int s = src[e], d = dst[e];
    float coef = g_edgebuf[e] / (g_asum[d] + 1e-9f);
    float4 v = reinterpret_cast<const float4*>(g_Wh2 + (size_t)s * D2)[sub];
    float* o = g_out2 + (size_t)d * D2 + sub * 4;
    atomicAdd(o + 0, coef * v.x);
    atomicAdd(o + 1, coef * v.y);
    atomicAdd(o + 2, coef * v.z);
    atomicAdd(o + 3, coef * v.w);
}

// ---------------- head: elu -> gelu(h@hw1+hb1) -> @hw2 + hb2 --------------
__global__ void k_head(const float* __restrict__ hw1,
                       const float* __restrict__ hb1,
                       const float* __restrict__ hw2,
                       const float* __restrict__ hb2,
                       float* __restrict__ out) {
    __shared__ float sw1[32 * 32];
    __shared__ float sb1[32];
    __shared__ float sw2[32];
    __shared__ float sh[8][32];
    int tid = threadIdx.x;
    for (int i = tid; i < 32 * 32; i += blockDim.x) sw1[i] = hw1[i];
    if (tid < 32) { sb1[tid] = hb1[tid]; sw2[tid] = hw2[tid]; }
    __syncthreads();

    int warp = tid >> 5, lane = tid & 31;
    int node = blockIdx.x * (blockDim.x >> 5) + warp;
    if (node >= NN) return;

    float h = g_out2[(size_t)node * D2 + lane];
    h = (h > 0.f) ? h : expm1f(h);
    sh[warp][lane] = h;
    __syncwarp();

    float acc = sb1[lane];
#pragma unroll 8
    for (int k = 0; k < 32; k++) acc += sh[warp][k] * sw1[k * 32 + lane];

    // exact gelu: 0.5*x*(1+erf(x/sqrt(2)))
    float z = 0.5f * acc * (1.f + erff(acc * 0.70710678118654752f));
    float sc = z * sw2[lane];
#pragma unroll
    for (int o = 16; o; o >>= 1) sc += __shfl_down_sync(0xffffffffu, sc, o);
    if (lane == 0) out[node] = sc + hb2[0];
}

// ---------------- launch ---------------------------------------------------
extern "C" void kernel_launch(void* const* d_in, const int* in_sizes, int n_in,
                              void* d_out, int out_size) {
    const float* x   = (const float*)d_in[0];
    const int* ei    = (const int*)d_in[1];     // int32! (JAX x64 disabled)
    const float* W1  = (const float*)d_in[2];
    const float* a1  = (const float*)d_in[3];
    const float* W2  = (const float*)d_in[4];
    const float* a2  = (const float*)d_in[5];
    const float* hw1 = (const float*)d_in[6];
    const float* hb1 = (const float*)d_in[7];
    const float* hw2 = (const float*)d_in[8];
    const float* hb2 = (const float*)d_in[9];
    float* out       = (float*)d_out;

    const int* src = ei;        // edge_index[0, :]
    const int* dst = ei + NE;   // edge_index[1, :]

    const int TB = 256;
    const int nodeBlocks = (NN + 7) / 8;          // warp per node, 8 warps/block
    const int edgeBlocks = (NE + TB - 1) / TB;    // thread per edge
    const int agg1Blocks = (int)(((size_t)NE * 32 + TB - 1) / TB);
    const int agg2Blocks = (int)(((size_t)NE * 8 + TB - 1) / TB);

    // layer 1
    k_node1<<<nodeBlocks, TB>>>(x, W1, a1);
    k_logit_max<<<edgeBlocks, TB>>>(src, dst, 1);
    k_exp_sum<<<edgeBlocks, TB>>>(dst);
    k_agg1<<<agg1Blocks, TB>>>(src, dst);

    // layer 2
    k_node2<<<nodeBlocks, TB>>>(W2, a2);
    k_logit_max<<<edgeBlocks, TB>>>(src, dst, 2);
    k_exp_sum<<<edgeBlocks, TB>>>(dst);
    k_agg2<<<agg2Blocks, TB>>>(src, dst);

    // head
    k_head<<<nodeBlocks, TB>>>(hw1, hb1, hw2, hb2, out);
}

// round 6
// speedup vs baseline: 1.4373x; 1.4373x over previous
#include <cuda_runtime.h>
#include <cuda_bf16.h>
#include <math.h>

#define NN 50000
#define NE 800000
#define D1 128
#define D2 32

// ---------------- scratch (device globals; no allocations) ----------------
__device__ __align__(16) float g_Wh1[(size_t)NN * D1];
__device__ __align__(16) float g_out1[(size_t)NN * D1];
__device__ __align__(16) float g_Wh2[(size_t)NN * D2];
__device__ __align__(16) float g_out2[(size_t)NN * D2];
__device__ float g_es1[NN], g_ed1[NN];
__device__ float g_es2[NN], g_ed2[NN];
__device__ float g_edgebuf[NE];      // logits, then exp(logit - max) in place
__device__ int   g_deg[NN];          // histogram, then scatter cursor
__device__ int   g_rowstart[NN + 1];
__device__ int   g_eid[NE];          // CSR: edge id per slot
__device__ int   g_csrc[NE];         // CSR: src node per slot
__device__ unsigned g_maxkey;

// order-preserving float->uint key (monotone under unsigned compare)
__device__ __forceinline__ unsigned f2key(float f) {
    unsigned b = __float_as_uint(f);
    return (b & 0x80000000u) ? ~b : (b | 0x80000000u);
}
__device__ __forceinline__ float key2f(unsigned k) {
    unsigned b = (k & 0x80000000u) ? (k ^ 0x80000000u) : ~k;
    return __uint_as_float(b);
}

// ================= CSR build (once per launch; topology fixed) ============
__global__ void k_zero_deg() {
    int i = blockIdx.x * blockDim.x + threadIdx.x;
    if (i < NN) g_deg[i] = 0;
}

__global__ void k_hist(const int* __restrict__ dst) {
    int e = blockIdx.x * blockDim.x + threadIdx.x;
    if (e < NE) atomicAdd(&g_deg[dst[e]], 1);
}

// single-block exclusive scan of g_deg -> g_rowstart; re-zeroes g_deg (cursor)
__global__ void k_scan() {
    const int T = 1024;
    const int CH = (NN + T - 1) / T;  // 49
    int t = threadIdx.x;
    int base = t * CH;

    int s = 0;
    for (int i = 0; i < CH; i++) {
        int idx = base + i;
        if (idx < NN) s += g_deg[idx];
    }
    // block exclusive scan of per-thread sums
    __shared__ int warpsum[32];
    int lane = t & 31, w = t >> 5;
    int incl = s;
#pragma unroll
    for (int o = 1; o < 32; o <<= 1) {
        int v = __shfl_up_sync(0xffffffffu, incl, o);
        if (lane >= o) incl += v;
    }
    if (lane == 31) warpsum[w] = incl;
    __syncthreads();
    if (w == 0) {
        int v = warpsum[lane];
#pragma unroll
        for (int o = 1; o < 32; o <<= 1) {
            int u = __shfl_up_sync(0xffffffffu, v, o);
            if (lane >= o) v += u;
        }
        warpsum[lane] = v;
    }
    __syncthreads();
    int excl = incl - s + ((w > 0) ? warpsum[w - 1] : 0);

    int run = excl;
    for (int i = 0; i < CH; i++) {
        int idx = base + i;
        if (idx < NN) {
            g_rowstart[idx] = run;
            run += g_deg[idx];
            g_deg[idx] = 0;  // becomes scatter cursor
        }
    }
    if (t == T - 1) g_rowstart[NN] = run;
}

__global__ void k_scatter(const int* __restrict__ src,
                          const int* __restrict__ dst) {
    int e = blockIdx.x * blockDim.x + threadIdx.x;
    if (e >= NE) return;
    int d = dst[e];
    int pos = g_rowstart[d] + atomicAdd(&g_deg[d], 1);
    g_eid[pos] = e;
    g_csrc[pos] = src[e];
}

// ================= layer 1 node: Wh1 = x @ W1, es/ed ======================
__global__ void k_node1(const float* __restrict__ x,
                        const float* __restrict__ W1,
                        const float* __restrict__ a1) {
    __shared__ float sW[8 * D1];
    __shared__ float sa[2 * D1];
    int tid = threadIdx.x;
    for (int i = tid; i < 8 * D1; i += blockDim.x) sW[i] = W1[i];
    for (int i = tid; i < 2 * D1; i += blockDim.x) sa[i] = a1[i];
    __syncthreads();

    if (blockIdx.x == 0 && tid == 0) g_maxkey = 0u;  // reset global max (layer 1)

    int warp = tid >> 5, lane = tid & 31;
    int node = blockIdx.x * (blockDim.x >> 5) + warp;
    if (node >= NN) return;

    float xr[8];
#pragma unroll
    for (int k = 0; k < 8; k++) xr[k] = x[node * 8 + k];

    float es = 0.f, ed = 0.f;
#pragma unroll
    for (int i = 0; i < 4; i++) {
        int j = i * 32 + lane;
        float acc = 0.f;
#pragma unroll
        for (int k = 0; k < 8; k++) acc += xr[k] * sW[k * D1 + j];
        g_Wh1[(size_t)node * D1 + j] = acc;
        es += acc * sa[j];
        ed += acc * sa[D1 + j];
    }
#pragma unroll
    for (int o = 16; o; o >>= 1) {
        es += __shfl_down_sync(0xffffffffu, es, o);
        ed += __shfl_down_sync(0xffffffffu, ed, o);
    }
    if (lane == 0) {
        g_es1[node] = es;
        g_ed1[node] = ed;
    }
}

// ================= edge logits + global max ===============================
__global__ void k_logit_max(const int* __restrict__ src,
                            const int* __restrict__ dst,
                            int layer) {
    const float* es = (layer == 1) ? g_es1 : g_es2;
    const float* ed = (layer == 1) ? g_ed1 : g_ed2;
    int e = blockIdx.x * blockDim.x + threadIdx.x;
    float v = -3.0e38f;
    if (e < NE) {
        int s = src[e], d = dst[e];
        float t = es[s] + ed[d];
        v = (t > 0.f) ? t : 0.2f * t;  // leaky_relu slope 0.2
        g_edgebuf[e] = v;
    }
    unsigned key = f2key(v);
#pragma unroll
    for (int o = 16; o; o >>= 1)
        key = max(key, __shfl_down_sync(0xffffffffu, key, o));
    if ((threadIdx.x & 31) == 0) atomicMax(&g_maxkey, key);
}

// ================= exp(logit - max), no atomics ===========================
__global__ void k_exp() {
    int e = blockIdx.x * blockDim.x + threadIdx.x;
    if (e >= NE) return;
    float m = key2f(g_maxkey);
    g_edgebuf[e] = expf(g_edgebuf[e] - m);
}

// ================= gather aggregation, D=128: warp per node ===============
// out1[n] = elu( (sum_e w_e * Wh1[src_e]) / (sum_e w_e + 1e-9) )
__global__ void k_gagg1() {
    int warp = threadIdx.x >> 5, lane = threadIdx.x & 31;
    int node = blockIdx.x * (blockDim.x >> 5) + warp;
    if (node >= NN) return;
    int beg = g_rowstart[node], end = g_rowstart[node + 1];

    float ax = 0.f, ay = 0.f, az = 0.f, aw = 0.f, asum = 0.f;
    for (int i = beg; i < end; i++) {
        int e = g_eid[i];
        int s = g_csrc[i];
        float w = g_edgebuf[e];
        asum += w;
        float4 v = reinterpret_cast<const float4*>(g_Wh1 + (size_t)s * D1)[lane];
        ax += w * v.x; ay += w * v.y; az += w * v.z; aw += w * v.w;
    }
    float inv = 1.f / (asum + 1e-9f);
    ax *= inv; ay *= inv; az *= inv; aw *= inv;
    // elu fused
    ax = (ax > 0.f) ? ax : expm1f(ax);
    ay = (ay > 0.f) ? ay : expm1f(ay);
    az = (az > 0.f) ? az : expm1f(az);
    aw = (aw > 0.f) ? aw : expm1f(aw);
    reinterpret_cast<float4*>(g_out1 + (size_t)node * D1)[lane] =
        make_float4(ax, ay, az, aw);
}

// ================= layer 2 node: Wh2 = out1 @ W2, es/ed ===================
__global__ void k_node2(const float* __restrict__ W2,
                        const float* __restrict__ a2) {
    __shared__ float sW[D1 * D2];  // 16 KB
    __shared__ float sa[2 * D2];
    __shared__ float sh[8][D1];
    int tid = threadIdx.x;
    for (int i = tid; i < D1 * D2; i += blockDim.x) sW[i] = W2[i];
    for (int i = tid; i < 2 * D2; i += blockDim.x) sa[i] = a2[i];
    __syncthreads();

    if (blockIdx.x == 0 && tid == 0) g_maxkey = 0u;  // reset for layer 2

    int warp = tid >> 5, lane = tid & 31;
    int node = blockIdx.x * (blockDim.x >> 5) + warp;
    if (node >= NN) return;

#pragma unroll
    for (int i = 0; i < 4; i++)  // out1 already elu'ed
        sh[warp][i * 32 + lane] = g_out1[(size_t)node * D1 + i * 32 + lane];
    __syncwarp();

    int j = lane;
    float acc = 0.f;
#pragma unroll 8
    for (int k = 0; k < D1; k++) acc += sh[warp][k] * sW[k * D2 + j];

    g_Wh2[(size_t)node * D2 + j] = acc;

    float es = acc * sa[j];
    float ed = acc * sa[D2 + j];
#pragma unroll
    for (int o = 16; o; o >>= 1) {
        es += __shfl_down_sync(0xffffffffu, es, o);
        ed += __shfl_down_sync(0xffffffffu, ed, o);
    }
    if (lane == 0) {
        g_es2[node] = es;
        g_ed2[node] = ed;
    }
}

// ================= gather aggregation, D=32: warp per node ================
__global__ void k_gagg2() {
    int warp = threadIdx.x >> 5, lane = threadIdx.x & 31;
    int node = blockIdx.x * (blockDim.x >> 5) + warp;
    if (node >= NN) return;
    int beg = g_rowstart[node], end = g_rowstart[node + 1];

    float acc = 0.f, asum = 0.f;
    for (int i = beg; i < end; i++) {
        int e = g_eid[i];
        int s = g_csrc[i];
        float w = g_edgebuf[e];
        asum += w;
        acc += w * g_Wh2[(size_t)s * D2 + lane];
    }
    acc *= 1.f / (asum + 1e-9f);
    acc = (acc > 0.f) ? acc : expm1f(acc);  // elu fused
    g_out2[(size_t)node * D2 + lane] = acc;
}

// ================= head: gelu(h@hw1+hb1) @ hw2 + hb2 ======================
__global__ void k_head(const float* __restrict__ hw1,
                       const float* __restrict__ hb1,
                       const float* __restrict__ hw2,
                       const float* __restrict__ hb2,
                       float* __restrict__ out) {
    __shared__ float sw1[32 * 32];
    __shared__ float sb1[32];
    __shared__ float sw2[32];
    __shared__ float sh[8][32];
    int tid = threadIdx.x;
    for (int i = tid; i < 32 * 32; i += blockDim.x) sw1[i] = hw1[i];
    if (tid < 32) { sb1[tid] = hb1[tid]; sw2[tid] = hw2[tid]; }
    __syncthreads();

    int warp = tid >> 5, lane = tid & 31;
    int node = blockIdx.x * (blockDim.x >> 5) + warp;
    if (node >= NN) return;

    sh[warp][lane] = g_out2[(size_t)node * D2 + lane];  // already elu'ed
    __syncwarp();

    float acc = sb1[lane];
#pragma unroll 8
    for (int k = 0; k < 32; k++) acc += sh[warp][k] * sw1[k * 32 + lane];

    // exact gelu: 0.5*x*(1+erf(x/sqrt(2)))
    float z = 0.5f * acc * (1.f + erff(acc * 0.70710678118654752f));
    float sc = z * sw2[lane];
#pragma unroll
    for (int o = 16; o; o >>= 1) sc += __shfl_down_sync(0xffffffffu, sc, o);
    if (lane == 0) out[node] = sc + hb2[0];
}

// ================= launch ==================================================
extern "C" void kernel_launch(void* const* d_in, const int* in_sizes, int n_in,
                              void* d_out, int out_size) {
    const float* x   = (const float*)d_in[0];
    const int* ei    = (const int*)d_in[1];     // int32 (JAX x64 disabled)
    const float* W1  = (const float*)d_in[2];
    const float* a1  = (const float*)d_in[3];
    const float* W2  = (const float*)d_in[4];
    const float* a2  = (const float*)d_in[5];
    const float* hw1 = (const float*)d_in[6];
    const float* hb1 = (const float*)d_in[7];
    const float* hw2 = (const float*)d_in[8];
    const float* hb2 = (const float*)d_in[9];
    float* out       = (float*)d_out;

    const int* src = ei;        // edge_index[0, :]
    const int* dst = ei + NE;   // edge_index[1, :]

    const int TB = 256;
    const int nodeBlocks = (NN + 7) / 8;        // warp per node, 8 warps/block
    const int edgeBlocks = (NE + TB - 1) / TB;  // thread per edge
    const int zeroBlocks = (NN + TB - 1) / TB;

    // CSR build (topology shared by both layers)
    k_zero_deg<<<zeroBlocks, TB>>>();
    k_hist<<<edgeBlocks, TB>>>(dst);
    k_scan<<<1, 1024>>>();
    k_scatter<<<edgeBlocks, TB>>>(src, dst);

    // layer 1
    k_node1<<<nodeBlocks, TB>>>(x, W1, a1);
    k_logit_max<<<edgeBlocks, TB>>>(src, dst, 1);
    k_exp<<<edgeBlocks, TB>>>();
    k_gagg1<<<nodeBlocks, TB>>>();

    // layer 2
    k_node2<<<nodeBlocks, TB>>>(W2, a2);
    k_logit_max<<<edgeBlocks, TB>>>(src, dst, 2);
    k_exp<<<edgeBlocks, TB>>>();
    k_gagg2<<<nodeBlocks, TB>>>();

    // head
    k_head<<<nodeBlocks, TB>>>(hw1, hb1, hw2, hb2, out);
}

// round 8
// speedup vs baseline: 1.8330x; 1.2753x over previous
#include <cuda_runtime.h>
#include <cuda_bf16.h>
#include <math.h>

#define NN 50000
#define NE 800000
#define D1 128
#define D2 32

// ---------------- scratch (device globals; no allocations) ----------------
__device__ __align__(16) float g_Wh1[(size_t)NN * D1];
__device__ __align__(16) float g_Wh2[(size_t)NN * D2];
__device__ float g_es1[NN], g_ed1[NN];
__device__ float g_es2[NN], g_ed2[NN];
__device__ int   g_deg[NN];          // histogram, then scatter cursor
__device__ int   g_rowstart[NN + 1];
__device__ int   g_csrc[NE];         // CSR: src node per slot (dst-sorted)

// ================= CSR build (per launch; topology shared by layers) ======
__global__ void k_zero_deg() {
    int i = blockIdx.x * blockDim.x + threadIdx.x;
    if (i < NN) g_deg[i] = 0;
}

__global__ void k_hist(const int* __restrict__ dst) {
    int e = blockIdx.x * blockDim.x + threadIdx.x;
    if (e < NE) atomicAdd(&g_deg[dst[e]], 1);
}

// single-block exclusive scan of g_deg -> g_rowstart; re-zeroes g_deg (cursor)
__global__ void k_scan() {
    const int T = 1024;
    const int CH = (NN + T - 1) / T;  // 49
    int t = threadIdx.x;
    int base = t * CH;

    int s = 0;
    for (int i = 0; i < CH; i++) {
        int idx = base + i;
        if (idx < NN) s += g_deg[idx];
    }
    __shared__ int warpsum[32];
    int lane = t & 31, w = t >> 5;
    int incl = s;
#pragma unroll
    for (int o = 1; o < 32; o <<= 1) {
        int v = __shfl_up_sync(0xffffffffu, incl, o);
        if (lane >= o) incl += v;
    }
    if (lane == 31) warpsum[w] = incl;
    __syncthreads();
    if (w == 0) {
        int v = warpsum[lane];
#pragma unroll
        for (int o = 1; o < 32; o <<= 1) {
            int u = __shfl_up_sync(0xffffffffu, v, o);
            if (lane >= o) v += u;
        }
        warpsum[lane] = v;
    }
    __syncthreads();
    int excl = incl - s + ((w > 0) ? warpsum[w - 1] : 0);

    int run = excl;
    for (int i = 0; i < CH; i++) {
        int idx = base + i;
        if (idx < NN) {
            g_rowstart[idx] = run;
            run += g_deg[idx];
            g_deg[idx] = 0;  // becomes scatter cursor
        }
    }
    if (t == T - 1) g_rowstart[NN] = run;
}

__global__ void k_scatter(const int* __restrict__ src,
                          const int* __restrict__ dst) {
    int e = blockIdx.x * blockDim.x + threadIdx.x;
    if (e >= NE) return;
    int d = dst[e];
    int pos = g_rowstart[d] + atomicAdd(&g_deg[d], 1);
    g_csrc[pos] = src[e];
}

// ================= layer 1 node: Wh1 = x @ W1, es1/ed1 ====================
__global__ void k_node1(const float* __restrict__ x,
                        const float* __restrict__ W1,
                        const float* __restrict__ a1) {
    __shared__ float sW[8 * D1];
    __shared__ float sa[2 * D1];
    int tid = threadIdx.x;
    for (int i = tid; i < 8 * D1; i += blockDim.x) sW[i] = W1[i];
    for (int i = tid; i < 2 * D1; i += blockDim.x) sa[i] = a1[i];
    __syncthreads();

    int warp = tid >> 5, lane = tid & 31;
    int node = blockIdx.x * (blockDim.x >> 5) + warp;
    if (node >= NN) return;

    float xr[8];
#pragma unroll
    for (int k = 0; k < 8; k++) xr[k] = x[node * 8 + k];

    float es = 0.f, ed = 0.f;
#pragma unroll
    for (int i = 0; i < 4; i++) {
        int j = i * 32 + lane;
        float acc = 0.f;
#pragma unroll
        for (int k = 0; k < 8; k++) acc += xr[k] * sW[k * D1 + j];
        g_Wh1[(size_t)node * D1 + j] = acc;
        es += acc * sa[j];
        ed += acc * sa[D1 + j];
    }
#pragma unroll
    for (int o = 16; o; o >>= 1) {
        es += __shfl_down_sync(0xffffffffu, es, o);
        ed += __shfl_down_sync(0xffffffffu, ed, o);
    }
    if (lane == 0) {
        g_es1[node] = es;
        g_ed1[node] = ed;
    }
}

// edge weight: exp(leaky_relu(logit)). Global max-shift dropped: the shift
// only enters through the +1e-9 denominator term (rel effect ~1e-10 here).
__device__ __forceinline__ float edge_w(float lg) {
    float v = (lg > 0.f) ? lg : 0.2f * lg;
    return __expf(v);
}

// ====== fused: gather-aggregate layer1 (D=128) + elu + node2 matvec =======
// out1[n] = elu( (Σ_e w_e Wh1[src_e]) / (Σ w_e + 1e-9) )   (kept in smem)
// Wh2[n]  = out1[n] @ W2 ;  es2/ed2 from a2
__global__ void k_gagg1_node2(const float* __restrict__ W2,
                              const float* __restrict__ a2) {
    __shared__ float sW[D1 * D2];   // 16 KB
    __shared__ float sa[2 * D2];
    __shared__ float sh[8][D1];     // per-warp out1 row
    int tid = threadIdx.x;
    for (int i = tid; i < D1 * D2; i += blockDim.x) sW[i] = W2[i];
    for (int i = tid; i < 2 * D2; i += blockDim.x) sa[i] = a2[i];
    __syncthreads();

    int warp = tid >> 5, lane = tid & 31;
    int node = blockIdx.x * (blockDim.x >> 5) + warp;
    if (node >= NN) return;

    int beg = g_rowstart[node], end = g_rowstart[node + 1];
    float edc = g_ed1[node];

    float ax = 0.f, ay = 0.f, az = 0.f, aw = 0.f, asum = 0.f;
#pragma unroll 2
    for (int i = beg; i < end; i++) {
        int s = g_csrc[i];
        float w = edge_w(g_es1[s] + edc);
        asum += w;
        float4 v = reinterpret_cast<const float4*>(g_Wh1 + (size_t)s * D1)[lane];
        ax += w * v.x; ay += w * v.y; az += w * v.z; aw += w * v.w;
    }
    float inv = 1.f / (asum + 1e-9f);
    ax *= inv; ay *= inv; az *= inv; aw *= inv;
    ax = (ax > 0.f) ? ax : expm1f(ax);   // elu fused
    ay = (ay > 0.f) ? ay : expm1f(ay);
    az = (az > 0.f) ? az : expm1f(az);
    aw = (aw > 0.f) ? aw : expm1f(aw);

    sh[warp][lane * 4 + 0] = ax;
    sh[warp][lane * 4 + 1] = ay;
    sh[warp][lane * 4 + 2] = az;
    sh[warp][lane * 4 + 3] = aw;
    __syncwarp();

    int j = lane;
    float acc = 0.f;
#pragma unroll 8
    for (int k = 0; k < D1; k++) acc += sh[warp][k] * sW[k * D2 + j];

    g_Wh2[(size_t)node * D2 + j] = acc;

    float es = acc * sa[j];
    float ed = acc * sa[D2 + j];
#pragma unroll
    for (int o = 16; o; o >>= 1) {
        es += __shfl_down_sync(0xffffffffu, es, o);
        ed += __shfl_down_sync(0xffffffffu, ed, o);
    }
    if (lane == 0) {
        g_es2[node] = es;
        g_ed2[node] = ed;
    }
}

// ====== fused: gather-aggregate layer2 (D=32) + elu + MLP head ============
__global__ void k_gagg2_head(const float* __restrict__ hw1,
                             const float* __restrict__ hb1,
                             const float* __restrict__ hw2,
                             const float* __restrict__ hb2,
                             float* __restrict__ out) {
    __shared__ float sw1[32 * 32];
    __shared__ float sb1[32];
    __shared__ float sw2[32];
    __shared__ float sh[8][32];
    int tid = threadIdx.x;
    for (int i = tid; i < 32 * 32; i += blockDim.x) sw1[i] = hw1[i];
    if (tid < 32) { sb1[tid] = hb1[tid]; sw2[tid] = hw2[tid]; }
    __syncthreads();

    int warp = tid >> 5, lane = tid & 31;
    int node = blockIdx.x * (blockDim.x >> 5) + warp;
    if (node >= NN) return;

    int beg = g_rowstart[node], end = g_rowstart[node + 1];
    float edc = g_ed2[node];

    float acc = 0.f, asum = 0.f;
#pragma unroll 2
    for (int i = beg; i < end; i++) {
        int s = g_csrc[i];
        float w = edge_w(g_es2[s] + edc);
        asum += w;
        acc += w * g_Wh2[(size_t)s * D2 + lane];
    }
    acc *= 1.f / (asum + 1e-9f);
    float h = (acc > 0.f) ? acc : expm1f(acc);   // elu fused

    sh[warp][lane] = h;
    __syncwarp();

    float z = sb1[lane];
#pragma unroll 8
    for (int k = 0; k < 32; k++) z += sh[warp][k] * sw1[k * 32 + lane];

    // exact gelu: 0.5*x*(1+erf(x/sqrt(2)))
    float g = 0.5f * z * (1.f + erff(z * 0.70710678118654752f));
    float sc = g * sw2[lane];
#pragma unroll
    for (int o = 16; o; o >>= 1) sc += __shfl_down_sync(0xffffffffu, sc, o);
    if (lane == 0) out[node] = sc + hb2[0];
}

// ================= launch ==================================================
extern "C" void kernel_launch(void* const* d_in, const int* in_sizes, int n_in,
                              void* d_out, int out_size) {
    const float* x   = (const float*)d_in[0];
    const int* ei    = (const int*)d_in[1];     // int32 (JAX x64 disabled)
    const float* W1  = (const float*)d_in[2];
    const float* a1  = (const float*)d_in[3];
    const float* W2  = (const float*)d_in[4];
    const float* a2  = (const float*)d_in[5];
    const float* hw1 = (const float*)d_in[6];
    const float* hb1 = (const float*)d_in[7];
    const float* hw2 = (const float*)d_in[8];
    const float* hb2 = (const float*)d_in[9];
    float* out       = (float*)d_out;

    const int* src = ei;        // edge_index[0, :]
    const int* dst = ei + NE;   // edge_index[1, :]

    const int TB = 256;
    const int nodeBlocks = (NN + 7) / 8;        // warp per node, 8 warps/block
    const int edgeBlocks = (NE + TB - 1) / TB;
    const int zeroBlocks = (NN + TB - 1) / TB;

    // CSR build
    k_zero_deg<<<zeroBlocks, TB>>>();
    k_hist<<<edgeBlocks, TB>>>(dst);
    k_scan<<<1, 1024>>>();
    k_scatter<<<edgeBlocks, TB>>>(src, dst);

    // layer 1 + fused layer-2 projection
    k_node1<<<nodeBlocks, TB>>>(x, W1, a1);
    k_gagg1_node2<<<nodeBlocks, TB>>>(W2, a2);

    // layer 2 gather + fused head
    k_gagg2_head<<<nodeBlocks, TB>>>(hw1, hb1, hw2, hb2, out);
}